// round 2
// baseline (speedup 1.0000x reference)
#include <cuda_runtime.h>

#define BB 4
#define TT 16
#define HH 64
#define WW 64
#define CC 32
#define FF 64
#define OC 256   // 4*F
#define SP 325   // shared plane stride (== 5 mod 32 -> conflict-free)

// ---------------- scratch (device globals; no allocations allowed) ----------
__device__ float g_xn[(size_t)BB*TT*HH*WW*CC];          // 8.4M
__device__ float g_zx[(size_t)BB*TT*HH*WW*OC];          // 67.1M (268MB)
__device__ float g_h [(size_t)BB*HH*WW*FF];             // 1M
__device__ float g_c [(size_t)BB*HH*WW*FF];             // 1M
__device__ float g_z [(size_t)BB*HH*WW*OC];             // 4.2M

// ---------------- LayerNorm over channel axis (C=32 = one warp) -------------
__global__ void ln_kernel(const float* __restrict__ x,
                          const float* __restrict__ gamma,
                          const float* __restrict__ beta) {
    int row  = blockIdx.x * 8 + (threadIdx.x >> 5);
    int lane = threadIdx.x & 31;
    float v = x[(size_t)row * CC + lane];
    float s = v, s2 = v * v;
    #pragma unroll
    for (int o = 16; o; o >>= 1) {
        s  += __shfl_xor_sync(0xffffffffu, s,  o);
        s2 += __shfl_xor_sync(0xffffffffu, s2, o);
    }
    float mu  = s * (1.f / 32.f);
    float var = s2 * (1.f / 32.f) - mu * mu;
    float inv = rsqrtf(var + 1e-3f);
    g_xn[(size_t)row * CC + lane] = (v - mu) * inv * gamma[lane] + beta[lane];
}

// ---------------- zero h, c --------------------------------------------------
__global__ void zero_hc_kernel() {
    int i = blockIdx.x * blockDim.x + threadIdx.x;
    if (i < BB * HH * WW * FF) { g_h[i] = 0.f; g_c[i] = 0.f; }
}

// ---------------- input conv: zx = conv3x3(xn, Wx) + b ----------------------
// grid: (ocb=8, tile=16, bt=64), block 256.  Tile 16x16, 32 out channels.
__global__ __launch_bounds__(256) void convx_kernel(const float* __restrict__ Wx,
                                                    const float* __restrict__ bias) {
    extern __shared__ float sm[];
    float* s_in = sm;                 // CC * SP
    float* s_w  = sm + CC * SP;       // 9*CC*32 = 9216

    int ocb  = blockIdx.x;
    int tile = blockIdx.y;
    int bt   = blockIdx.z;
    int tid  = threadIdx.x;
    int ty0 = (tile >> 2) * 16, tx0 = (tile & 3) * 16;
    int oc0 = ocb * 32;

    for (int i = tid; i < 9 * CC * 32; i += 256) {
        int oc = i & 31, rest = i >> 5;             // rest = kpos*CC + ic
        s_w[i] = Wx[(size_t)rest * OC + oc0 + oc];
    }
    const float* xin = g_xn + (size_t)bt * HH * WW * CC;
    for (int i = tid; i < CC * 324; i += 256) {
        int ch = i / 324, sp = i - ch * 324;
        int gy = ty0 - 1 + sp / 18, gx = tx0 - 1 + sp % 18;
        float v = 0.f;
        if (gy >= 0 && gy < HH && gx >= 0 && gx < WW)
            v = xin[((size_t)gy * WW + gx) * CC + ch];
        s_in[ch * SP + sp] = v;
    }
    __syncthreads();

    int px = tid & 15, py = tid >> 4;
    float acc[32];
    #pragma unroll
    for (int oc = 0; oc < 32; oc++) acc[oc] = bias[oc0 + oc];

    for (int kp = 0; kp < 9; kp++) {
        int ky = kp / 3, kx = kp - 3 * ky;
        int spb = (py + ky) * 18 + px + kx;
        const float* wrow = s_w + kp * CC * 32;
        for (int ic = 0; ic < CC; ic++) {
            float a = s_in[ic * SP + spb];
            const float4* w4 = (const float4*)(wrow + ic * 32);
            #pragma unroll
            for (int j = 0; j < 8; j++) {
                float4 w = w4[j];
                acc[4*j+0] += a * w.x; acc[4*j+1] += a * w.y;
                acc[4*j+2] += a * w.z; acc[4*j+3] += a * w.w;
            }
        }
    }
    float* zp = g_zx + ((((size_t)bt) * HH + ty0 + py) * WW + tx0 + px) * OC + oc0;
    #pragma unroll
    for (int j = 0; j < 8; j++)
        ((float4*)zp)[j] = make_float4(acc[4*j], acc[4*j+1], acc[4*j+2], acc[4*j+3]);
}

// ---------------- recurrent conv: z = zx[:,t] + conv3x3(h, Wh) --------------
// grid: (ocb=8, tile=16, b=4), block 256.
__global__ __launch_bounds__(256) void convh_kernel(const float* __restrict__ Wh, int t) {
    extern __shared__ float sm[];
    float* s_in = sm;                 // FF * SP
    float* s_w  = sm + FF * SP;       // 9*FF*32 = 18432

    int ocb  = blockIdx.x;
    int tile = blockIdx.y;
    int b    = blockIdx.z;
    int tid  = threadIdx.x;
    int ty0 = (tile >> 2) * 16, tx0 = (tile & 3) * 16;
    int oc0 = ocb * 32;

    for (int i = tid; i < 9 * FF * 32; i += 256) {
        int oc = i & 31, rest = i >> 5;             // rest = kpos*FF + ic
        s_w[i] = Wh[(size_t)rest * OC + oc0 + oc];
    }
    const float* hin = g_h + (size_t)b * HH * WW * FF;
    for (int i = tid; i < FF * 324; i += 256) {
        int ch = i / 324, sp = i - ch * 324;
        int gy = ty0 - 1 + sp / 18, gx = tx0 - 1 + sp % 18;
        float v = 0.f;
        if (gy >= 0 && gy < HH && gx >= 0 && gx < WW)
            v = hin[((size_t)gy * WW + gx) * FF + ch];
        s_in[ch * SP + sp] = v;
    }
    __syncthreads();

    int px = tid & 15, py = tid >> 4;
    int y = ty0 + py, x = tx0 + px;

    float acc[32];
    const float4* zx4 = (const float4*)(g_zx +
        (((((size_t)b * TT) + t) * HH + y) * WW + x) * OC + oc0);
    #pragma unroll
    for (int j = 0; j < 8; j++) {
        float4 v = zx4[j];
        acc[4*j+0] = v.x; acc[4*j+1] = v.y; acc[4*j+2] = v.z; acc[4*j+3] = v.w;
    }

    for (int kp = 0; kp < 9; kp++) {
        int ky = kp / 3, kx = kp - 3 * ky;
        int spb = (py + ky) * 18 + px + kx;
        const float* wrow = s_w + kp * FF * 32;
        for (int ic = 0; ic < FF; ic++) {
            float a = s_in[ic * SP + spb];
            const float4* w4 = (const float4*)(wrow + ic * 32);
            #pragma unroll
            for (int j = 0; j < 8; j++) {
                float4 w = w4[j];
                acc[4*j+0] += a * w.x; acc[4*j+1] += a * w.y;
                acc[4*j+2] += a * w.z; acc[4*j+3] += a * w.w;
            }
        }
    }
    float* zp = g_z + (((size_t)b * HH + y) * WW + x) * OC + oc0;
    #pragma unroll
    for (int j = 0; j < 8; j++)
        ((float4*)zp)[j] = make_float4(acc[4*j], acc[4*j+1], acc[4*j+2], acc[4*j+3]);
}

// ---------------- LSTM gates ------------------------------------------------
__global__ void gate_kernel() {
    int i = blockIdx.x * blockDim.x + threadIdx.x;   // over B*H*W*F
    if (i >= BB * HH * WW * FF) return;
    int f = i & 63;
    int pos = i >> 6;
    const float* z = g_z + (size_t)pos * OC;
    float zi = z[f], zf = z[64 + f], zc = z[128 + f], zo = z[192 + f];
    float ig = __saturatef(0.2f * zi + 0.5f);
    float fg = __saturatef(0.2f * zf + 0.5f);
    float og = __saturatef(0.2f * zo + 0.5f);
    float c  = fg * g_c[i] + ig * tanhf(zc);
    g_c[i] = c;
    g_h[i] = og * tanhf(c);
}

// ---------------- MaxPool (1,2,2) for one timestep --------------------------
__global__ void pool_kernel(float* __restrict__ out, int t) {
    int i = blockIdx.x * blockDim.x + threadIdx.x;   // B*32*32*F = 262144
    if (i >= BB * 32 * 32 * FF) return;
    int f = i & 63;
    int r = i >> 6;
    int xo = r & 31; r >>= 5;
    int yo = r & 31;
    int b  = r >> 5;
    const float* hp = g_h + (((size_t)b * HH + yo * 2) * WW + xo * 2) * FF + f;
    float m = fmaxf(fmaxf(hp[0], hp[FF]),
                    fmaxf(hp[(size_t)WW * FF], hp[(size_t)WW * FF + FF]));
    out[(((((size_t)b * TT) + t) * 32 + yo) * 32 + xo) * FF + f] = m;
}

// ---------------- launch ----------------------------------------------------
extern "C" void kernel_launch(void* const* d_in, const int* in_sizes, int n_in,
                              void* d_out, int out_size) {
    const float* x     = (const float*)d_in[0];
    const float* gamma = (const float*)d_in[1];
    const float* beta  = (const float*)d_in[2];
    const float* Wx    = (const float*)d_in[3];
    const float* Wh    = (const float*)d_in[4];
    const float* bias  = (const float*)d_in[5];
    float* out = (float*)d_out;

    const int SMEM_X = (CC * SP + 9 * CC * 32) * 4;   // 78464 B
    const int SMEM_H = (FF * SP + 9 * FF * 32) * 4;   // 156928 B
    cudaFuncSetAttribute(convx_kernel, cudaFuncAttributeMaxDynamicSharedMemorySize, SMEM_X);
    cudaFuncSetAttribute(convh_kernel, cudaFuncAttributeMaxDynamicSharedMemorySize, SMEM_H);

    // LayerNorm
    ln_kernel<<<(BB * TT * HH * WW) / 8, 256>>>(x, gamma, beta);

    // zero h, c (must happen every call: deterministic)
    zero_hc_kernel<<<(BB * HH * WW * FF + 255) / 256, 256>>>();

    // input conv over all timesteps at once
    convx_kernel<<<dim3(8, 16, BB * TT), 256, SMEM_X>>>(Wx, bias);

    // recurrent loop
    for (int t = 0; t < TT; t++) {
        convh_kernel<<<dim3(8, 16, BB), 256, SMEM_H>>>(Wh, t);
        gate_kernel<<<(BB * HH * WW * FF + 255) / 256, 256>>>();
        pool_kernel<<<(BB * 32 * 32 * FF + 255) / 256, 256>>>(out, t);
    }
}